// round 12
// baseline (speedup 1.0000x reference)
#include <cuda_runtime.h>
#include <cstdint>
#include <math.h>

// Problem constants
#define BB 2
#define SS 2048
#define DD 1024
#define HH 16
#define HD 64

// Scratch (allocation-free rule: __device__ globals)
__device__ float g_qkv[(size_t)3 * BB * HH * SS * HD];   // [3][B][H][S][HD] (tf32-rounded)
__device__ float g_attn[(size_t)BB * SS * DD];           // [B][S][D]       (tf32-rounded)
__device__ float g_xr[(size_t)BB * SS * DD];             // rounded x
__device__ float g_wq[(size_t)3 * DD * DD];              // rounded w_qkv
__device__ float g_wp[(size_t)DD * DD];                  // rounded w_proj

#define HEAD_ELEMS ((size_t)SS * HD)
#define QKV_ONE    ((size_t)BB * HH * SS * HD)

// ===========================================================================
// Helpers
// ===========================================================================
__device__ __forceinline__ uint32_t smem_u32(const void* p) {
    uint32_t a;
    asm("{ .reg .u64 t; cvta.to.shared.u64 t, %1; cvt.u32.u64 %0, t; }"
        : "=r"(a) : "l"(p));
    return a;
}
__device__ __forceinline__ float tf32_rna(float x) {
    uint32_t u;
    asm("cvt.rna.tf32.f32 %0, %1;" : "=r"(u) : "f"(x));
    return __uint_as_float(u);
}
__device__ __forceinline__ float4 tf32_rna4(float4 v) {
    v.x = tf32_rna(v.x); v.y = tf32_rna(v.y);
    v.z = tf32_rna(v.z); v.w = tf32_rna(v.w);
    return v;
}

#define CP_ASYNC16(saddr, gptr) \
    asm volatile("cp.async.ca.shared.global [%0], [%1], 16;" \
                 :: "r"(saddr), "l"(gptr) : "memory")
#define CP_COMMIT() asm volatile("cp.async.commit_group;" ::: "memory")
#define CP_WAIT1()  asm volatile("cp.async.wait_group 1;" ::: "memory")
#define CP_WAIT0()  asm volatile("cp.async.wait_group 0;" ::: "memory")

// TF32 mma.sync (m16n8k8): A row-major, B col-major, fp32 accum.
// Fragment layout (g = lane>>2, t4 = lane&3):
//   A: a0=(g,t4) a1=(g+8,t4) a2=(g,t4+4) a3=(g+8,t4+4)
//   B: b0=(k=t4,n=g) b1=(k=t4+4,n=g)
//   C: c0=(g,2t4) c1=(g,2t4+1) c2=(g+8,2t4) c3=(g+8,2t4+1)
__device__ __forceinline__ void mma_tf32(float* d, const uint32_t* a,
                                         const uint32_t* b) {
    asm volatile(
        "mma.sync.aligned.m16n8k8.row.col.f32.tf32.tf32.f32 "
        "{%0,%1,%2,%3}, {%4,%5,%6,%7}, {%8,%9}, {%0,%1,%2,%3};"
        : "+f"(d[0]), "+f"(d[1]), "+f"(d[2]), "+f"(d[3])
        : "r"(a[0]), "r"(a[1]), "r"(a[2]), "r"(a[3]), "r"(b[0]), "r"(b[1]));
}

// ===========================================================================
// Prepass: round fp32 -> tf32 bit patterns (removes in-loop cvts downstream)
// ===========================================================================
__global__ void round_kernel(const float* __restrict__ src,
                             float* __restrict__ dst, int n4)
{
    const int stride = gridDim.x * blockDim.x;
    for (int i = blockIdx.x * blockDim.x + threadIdx.x; i < n4; i += stride)
        ((float4*)dst)[i] = tf32_rna4(((const float4*)src)[i]);
}

// ===========================================================================
// GEMM: C[128x128] = A[128xK] . W[128xK]^T + bias.  K = 1024.
// Inputs pre-rounded to tf32. cp.async 2-stage double-buffered staging.
// 256 threads, 8 warps in 2(M) x 4(N); warp tile 64x32 (4x4 m16n8 tiles).
// MODE 0: scatter epilogue into g_qkv (rounded).  MODE 1: row-major out.
// ===========================================================================
#define GEMM_K 1024
#define ASTR   36                          // 144B row stride (16B-aligned)
#define GTILE  (128 * ASTR)                // floats per tile buffer
#define GEMM_SMEM (4 * GTILE * (int)sizeof(float))   // 73728 B

template <int MODE>
__global__ __launch_bounds__(256, 2) void tc_gemm_kernel(
    const float* __restrict__ A, const float* __restrict__ W,
    const float* __restrict__ bias, float* __restrict__ out)
{
    extern __shared__ float smem[];
    const uint32_t sb = smem_u32(smem);

    const int tid = threadIdx.x;
    const int wid = tid >> 5;
    const int lane = tid & 31;
    const int g = lane >> 2;
    const int t4 = lane & 3;
    const int warpM = wid >> 2;       // 0..1
    const int warpN = wid & 3;        // 0..3
    const int m0 = blockIdx.y << 7;
    const int n0 = blockIdx.x << 7;

    // buffers: A0 | B0 | A1 | B1
    float* bufA[2] = { smem,             smem + 2 * GTILE };
    float* bufB[2] = { smem + GTILE,     smem + 3 * GTILE };
    const uint32_t sA[2] = { sb,                     sb + 2u * GTILE * 4u };
    const uint32_t sB[2] = { sb + (uint32_t)GTILE*4, sb + 3u * GTILE * 4u };

    const float* aBase = A + (size_t)m0 * GEMM_K;
    const float* wBase = W + (size_t)n0 * GEMM_K;

    // per-thread staging: e = tid + i*256 -> row = e>>3, c4 = e&7
    const int srow = tid >> 3;
    const int sc4 = tid & 7;

    auto stage = [&](int s, int b) {
        const int k0 = s * 32;
        #pragma unroll
        for (int i = 0; i < 4; ++i) {
            const int row = srow + i * 32;
            const uint32_t so = (uint32_t)(row * ASTR + sc4 * 4) * 4u;
            CP_ASYNC16(sA[b] + so, aBase + (size_t)row * GEMM_K + k0 + sc4 * 4);
            CP_ASYNC16(sB[b] + so, wBase + (size_t)row * GEMM_K + k0 + sc4 * 4);
        }
        CP_COMMIT();
    };

    float acc[4][4][4] = {};

    stage(0, 0);
    for (int s = 0; s < GEMM_K / 32; ++s) {
        if (s + 1 < GEMM_K / 32) { stage(s + 1, (s + 1) & 1); CP_WAIT1(); }
        else                     { CP_WAIT0(); }
        __syncthreads();

        const float* aS = bufA[s & 1];
        const float* bS = bufB[s & 1];
        #pragma unroll
        for (int kc = 0; kc < 4; ++kc) {
            uint32_t afr[4][4], bfr[4][2];
            #pragma unroll
            for (int mt = 0; mt < 4; ++mt) {
                const float* p = &aS[(warpM * 64 + mt * 16 + g) * ASTR + kc * 8 + t4];
                afr[mt][0] = __float_as_uint(p[0]);
                afr[mt][1] = __float_as_uint(p[8 * ASTR]);
                afr[mt][2] = __float_as_uint(p[4]);
                afr[mt][3] = __float_as_uint(p[8 * ASTR + 4]);
            }
            #pragma unroll
            for (int nt = 0; nt < 4; ++nt) {
                const float* p = &bS[(warpN * 32 + nt * 8 + g) * ASTR + kc * 8 + t4];
                bfr[nt][0] = __float_as_uint(p[0]);
                bfr[nt][1] = __float_as_uint(p[4]);
            }
            #pragma unroll
            for (int mt = 0; mt < 4; ++mt)
                #pragma unroll
                for (int nt = 0; nt < 4; ++nt)
                    mma_tf32(acc[mt][nt], afr[mt], bfr[nt]);
        }
        __syncthreads();
    }

    // Epilogue
    #pragma unroll
    for (int mt = 0; mt < 4; ++mt) {
        const int r0 = m0 + warpM * 64 + mt * 16 + g;
        const int r1 = r0 + 8;
        #pragma unroll
        for (int nt = 0; nt < 4; ++nt) {
            const int n = n0 + warpN * 32 + nt * 8 + t4 * 2;
            const float bn0 = bias[n], bn1 = bias[n + 1];
            const float v00 = acc[mt][nt][0] + bn0;
            const float v01 = acc[mt][nt][1] + bn1;
            const float v10 = acc[mt][nt][2] + bn0;
            const float v11 = acc[mt][nt][3] + bn1;
            if (MODE == 0) {
                // round at producer: consumers (flash) need tf32 operands
                const int which = n >> 10;
                const int rn = n & 1023;
                const int h = rn >> 6;
                const int d = rn & 63;
                const int b = r0 >> 11;
                const size_t base = ((((size_t)which * BB + b) * HH + h) * SS);
                size_t i0 = (base + (r0 & 2047)) * HD + d;
                size_t i1 = (base + (r1 & 2047)) * HD + d;
                g_qkv[i0] = tf32_rna(v00); g_qkv[i0 + 1] = tf32_rna(v01);
                g_qkv[i1] = tf32_rna(v10); g_qkv[i1 + 1] = tf32_rna(v11);
            } else {
                out[(size_t)r0 * DD + n] = v00;
                out[(size_t)r0 * DD + n + 1] = v01;
                out[(size_t)r1 * DD + n] = v10;
                out[(size_t)r1 * DD + n + 1] = v11;
            }
        }
    }
}

// ===========================================================================
// Flash attention on mma.sync TF32, cp.async double-buffered K/V.
// 128 queries x 64 keys per tile. 256 threads; warp w owns q-rows w*16..+15.
// Q fragments in registers; Q smem region reused as the P buffer.
// grid = (S/128, B*H) = (16, 32).
// ===========================================================================
#define FSTR 68                            // 272B row stride (16B-aligned)
#define KVTILE (64 * FSTR)
// layout: QP(128*FSTR) | K0 | V0 | K1 | V1
#define FLASH_SMEM ((128 * FSTR + 4 * KVTILE) * (int)sizeof(float))  // 104448

__global__ __launch_bounds__(256, 2) void flash_attn_kernel()
{
    extern __shared__ float sm[];
    float* QP = sm;
    float* Kbuf[2] = { sm + 128 * FSTR,              sm + 128 * FSTR + 2 * KVTILE };
    float* Vbuf[2] = { sm + 128 * FSTR + KVTILE,     sm + 128 * FSTR + 3 * KVTILE };
    const uint32_t sb = smem_u32(sm);
    const uint32_t sK[2] = { sb + 128u * FSTR * 4u,
                             sb + (128u * FSTR + 2u * KVTILE) * 4u };
    const uint32_t sV[2] = { sb + (128u * FSTR + KVTILE) * 4u,
                             sb + (128u * FSTR + 3u * KVTILE) * 4u };

    const int tid = threadIdx.x;
    const int wid = tid >> 5;
    const int lane = tid & 31;
    const int g = lane >> 2;
    const int t4 = lane & 3;
    const int q0 = blockIdx.x << 7;
    const int bh = blockIdx.y;
    const int b = bh >> 4, h = bh & 15;

    const size_t head_off = (size_t)(b * HH + h) * HEAD_ELEMS;
    const float* Qg = g_qkv + head_off;
    const float* Kg = g_qkv + QKV_ONE + head_off;
    const float* Vg = g_qkv + 2 * QKV_ONE + head_off;

    // Stage Q tile [128][64] (already tf32-rounded by producer)
    #pragma unroll
    for (int i = 0; i < 8; ++i) {
        const int e = tid + i * 256;
        const int row = e >> 4;
        const int c4 = e & 15;
        *(float4*)&QP[row * FSTR + c4 * 4] =
            *(const float4*)(Qg + (size_t)(q0 + row) * HD + c4 * 4);
    }

    // K/V staging assignment: e = tid + i*256 -> row = e>>4, c4 = e&15
    const int krow = tid >> 4;
    const int kc4 = tid & 15;
    auto stageKV = [&](int kt, int bsel) {
        #pragma unroll
        for (int i = 0; i < 4; ++i) {
            const int row = krow + i * 16;
            const uint32_t so = (uint32_t)(row * FSTR + kc4 * 4) * 4u;
            const size_t gi = (size_t)(kt * 64 + row) * HD + kc4 * 4;
            CP_ASYNC16(sK[bsel] + so, Kg + gi);
            CP_ASYNC16(sV[bsel] + so, Vg + gi);
        }
        CP_COMMIT();
    };

    stageKV(0, 0);
    __syncthreads();   // Q staged (regular STS) visible to all

    // Q fragments for all 8 k-chunks (warp-private rows)
    uint32_t qf[8][4];
    #pragma unroll
    for (int kc = 0; kc < 8; ++kc) {
        const float* p = &QP[(wid * 16 + g) * FSTR + kc * 8 + t4];
        qf[kc][0] = __float_as_uint(p[0]);
        qf[kc][1] = __float_as_uint(p[8 * FSTR]);
        qf[kc][2] = __float_as_uint(p[4]);
        qf[kc][3] = __float_as_uint(p[8 * FSTR + 4]);
    }

    float oacc[8][4] = {};
    float mr0 = -1e30f, mr1 = -1e30f, l0 = 0.0f, l1 = 0.0f;
    const float scale = 0.125f;

    for (int kt = 0; kt < SS / 64; ++kt) {
        if (kt + 1 < SS / 64) { stageKV(kt + 1, (kt + 1) & 1); CP_WAIT1(); }
        else                  { CP_WAIT0(); }
        __syncthreads();   // K/V[kt&1] visible; also orders qf loads (kt=0) and
                           // prior compute before this buffer's next overwrite

        const float* Ks = Kbuf[kt & 1];
        const float* Vs = Vbuf[kt & 1];

        // S = Q . K^T : warp computes 16x64 scores
        float sacc[8][4] = {};
        #pragma unroll
        for (int kc = 0; kc < 8; ++kc) {
            #pragma unroll
            for (int nt = 0; nt < 8; ++nt) {
                const float* p = &Ks[(nt * 8 + g) * FSTR + kc * 8 + t4];
                uint32_t bfr[2];
                bfr[0] = __float_as_uint(p[0]);
                bfr[1] = __float_as_uint(p[4]);
                mma_tf32(sacc[nt], qf[kc], bfr);
            }
        }

        // Online softmax. Row g: regs [0],[1]; row g+8: regs [2],[3].
        float mx0 = -1e30f, mx1 = -1e30f;
        #pragma unroll
        for (int nt = 0; nt < 8; ++nt) {
            sacc[nt][0] *= scale; sacc[nt][1] *= scale;
            sacc[nt][2] *= scale; sacc[nt][3] *= scale;
            mx0 = fmaxf(mx0, fmaxf(sacc[nt][0], sacc[nt][1]));
            mx1 = fmaxf(mx1, fmaxf(sacc[nt][2], sacc[nt][3]));
        }
        mx0 = fmaxf(mx0, __shfl_xor_sync(0xffffffffu, mx0, 1));
        mx0 = fmaxf(mx0, __shfl_xor_sync(0xffffffffu, mx0, 2));
        mx1 = fmaxf(mx1, __shfl_xor_sync(0xffffffffu, mx1, 1));
        mx1 = fmaxf(mx1, __shfl_xor_sync(0xffffffffu, mx1, 2));

        const float mn0 = fmaxf(mr0, mx0);
        const float mn1 = fmaxf(mr1, mx1);
        const float corr0 = __expf(mr0 - mn0);
        const float corr1 = __expf(mr1 - mn1);
        mr0 = mn0; mr1 = mn1;

        float rs0 = 0.0f, rs1 = 0.0f;
        #pragma unroll
        for (int nt = 0; nt < 8; ++nt) {
            sacc[nt][0] = __expf(sacc[nt][0] - mn0);
            sacc[nt][1] = __expf(sacc[nt][1] - mn0);
            sacc[nt][2] = __expf(sacc[nt][2] - mn1);
            sacc[nt][3] = __expf(sacc[nt][3] - mn1);
            rs0 += sacc[nt][0] + sacc[nt][1];
            rs1 += sacc[nt][2] + sacc[nt][3];
        }
        rs0 += __shfl_xor_sync(0xffffffffu, rs0, 1);
        rs0 += __shfl_xor_sync(0xffffffffu, rs0, 2);
        rs1 += __shfl_xor_sync(0xffffffffu, rs1, 1);
        rs1 += __shfl_xor_sync(0xffffffffu, rs1, 2);

        l0 = l0 * corr0 + rs0;
        l1 = l1 * corr1 + rs1;

        #pragma unroll
        for (int nt = 0; nt < 8; ++nt) {
            oacc[nt][0] *= corr0; oacc[nt][1] *= corr0;
            oacc[nt][2] *= corr1; oacc[nt][3] *= corr1;
        }

        // P -> smem (warp-private rows; QP reused), rounded to tf32
        __syncwarp();
        {
            const int row = wid * 16 + g;
            #pragma unroll
            for (int nt = 0; nt < 8; ++nt) {
                const int col = nt * 8 + t4 * 2;
                QP[row * FSTR + col]           = tf32_rna(sacc[nt][0]);
                QP[row * FSTR + col + 1]       = tf32_rna(sacc[nt][1]);
                QP[(row + 8) * FSTR + col]     = tf32_rna(sacc[nt][2]);
                QP[(row + 8) * FSTR + col + 1] = tf32_rna(sacc[nt][3]);
            }
        }
        __syncwarp();

        // O += P . V
        #pragma unroll
        for (int kc = 0; kc < 8; ++kc) {
            uint32_t af[4];
            const float* p = &QP[(wid * 16 + g) * FSTR + kc * 8 + t4];
            af[0] = __float_as_uint(p[0]);
            af[1] = __float_as_uint(p[8 * FSTR]);
            af[2] = __float_as_uint(p[4]);
            af[3] = __float_as_uint(p[8 * FSTR + 4]);
            #pragma unroll
            for (int nt = 0; nt < 8; ++nt) {
                const float* vp = &Vs[(kc * 8 + t4) * FSTR + nt * 8 + g];
                uint32_t bfr[2];
                bfr[0] = __float_as_uint(vp[0]);
                bfr[1] = __float_as_uint(vp[4 * FSTR]);
                mma_tf32(oacc[nt], af, bfr);
            }
        }
        __syncthreads();   // all reads of buf[kt&1] done before its re-stage
    }

    // Epilogue: normalize, round (feeds proj GEMM), write [B,S,H*hd]
    const float inv0 = 1.0f / l0;
    const float inv1 = 1.0f / l1;
    const int row0 = q0 + wid * 16 + g;
    const int row1 = row0 + 8;
    #pragma unroll
    for (int nt = 0; nt < 8; ++nt) {
        const int col = h * HD + nt * 8 + t4 * 2;
        float* o0 = &g_attn[((size_t)b * SS + row0) * DD + col];
        float* o1 = &g_attn[((size_t)b * SS + row1) * DD + col];
        o0[0] = tf32_rna(oacc[nt][0] * inv0); o0[1] = tf32_rna(oacc[nt][1] * inv0);
        o1[0] = tf32_rna(oacc[nt][2] * inv1); o1[1] = tf32_rna(oacc[nt][3] * inv1);
    }
}

// ---------------------------------------------------------------------------
// Launch
// ---------------------------------------------------------------------------
extern "C" void kernel_launch(void* const* d_in, const int* in_sizes, int n_in,
                              void* d_out, int out_size)
{
    (void)in_sizes; (void)n_in; (void)out_size;
    const float* x      = (const float*)d_in[0];
    const float* w_qkv  = (const float*)d_in[1];
    const float* b_qkv  = (const float*)d_in[2];
    const float* w_proj = (const float*)d_in[3];
    const float* b_proj = (const float*)d_in[4];
    float* out = (float*)d_out;

    cudaFuncSetAttribute(tc_gemm_kernel<0>,
                         cudaFuncAttributeMaxDynamicSharedMemorySize, GEMM_SMEM);
    cudaFuncSetAttribute(tc_gemm_kernel<1>,
                         cudaFuncAttributeMaxDynamicSharedMemorySize, GEMM_SMEM);
    cudaFuncSetAttribute(flash_attn_kernel,
                         cudaFuncAttributeMaxDynamicSharedMemorySize, FLASH_SMEM);

    float *xr, *wq, *wp, *attn_ptr;
    cudaGetSymbolAddress((void**)&xr, g_xr);
    cudaGetSymbolAddress((void**)&wq, g_wq);
    cudaGetSymbolAddress((void**)&wp, g_wp);
    cudaGetSymbolAddress((void**)&attn_ptr, g_attn);

    // 0) Pre-round inputs to tf32 (removes all in-loop cvts)
    round_kernel<<<1024, 256>>>(x, xr, BB * SS * DD / 4);
    round_kernel<<<1024, 256>>>(w_qkv, wq, 3 * DD * DD / 4);
    round_kernel<<<512, 256>>>(w_proj, wp, DD * DD / 4);

    // 1) QKV projection: M=4096, N=3072 -> grid (24, 32)
    tc_gemm_kernel<0><<<dim3(3 * DD / 128, BB * SS / 128), 256, GEMM_SMEM>>>(
        xr, wq, b_qkv, nullptr);

    // 2) Flash attention: grid (16, 32)
    flash_attn_kernel<<<dim3(SS / 128, BB * HH), 256, FLASH_SMEM>>>();

    // 3) Output projection: M=4096, N=1024 -> grid (8, 32)
    tc_gemm_kernel<1><<<dim3(DD / 128, BB * SS / 128), 256, GEMM_SMEM>>>(
        attn_ptr, wp, b_proj, out);
}

// round 16
// speedup vs baseline: 1.1742x; 1.1742x over previous
#include <cuda_runtime.h>
#include <cstdint>
#include <math.h>

// Problem constants
#define BB 2
#define SS 2048
#define DD 1024
#define HH 16
#define HD 64

// Scratch (allocation-free rule: __device__ globals)
__device__ float g_qkv[(size_t)3 * BB * HH * SS * HD];   // [3][B][H][S][HD] (tf32-rounded)
__device__ float g_attn[(size_t)BB * SS * DD];           // [B][S][D]       (tf32-rounded)
__device__ float g_xr[(size_t)BB * SS * DD];             // rounded x
__device__ float g_wq[(size_t)3 * DD * DD];              // rounded w_qkv
__device__ float g_wp[(size_t)DD * DD];                  // rounded w_proj

#define HEAD_ELEMS ((size_t)SS * HD)
#define QKV_ONE    ((size_t)BB * HH * SS * HD)

// ===========================================================================
// Helpers
// ===========================================================================
__device__ __forceinline__ uint32_t smem_u32(const void* p) {
    uint32_t a;
    asm("{ .reg .u64 t; cvta.to.shared.u64 t, %1; cvt.u32.u64 %0, t; }"
        : "=r"(a) : "l"(p));
    return a;
}
__device__ __forceinline__ float tf32_rna(float x) {
    uint32_t u;
    asm("cvt.rna.tf32.f32 %0, %1;" : "=r"(u) : "f"(x));
    return __uint_as_float(u);
}
__device__ __forceinline__ float4 tf32_rna4(float4 v) {
    v.x = tf32_rna(v.x); v.y = tf32_rna(v.y);
    v.z = tf32_rna(v.z); v.w = tf32_rna(v.w);
    return v;
}

// ldmatrix x4: 4 8x8 b16 tiles == 4 8x4 f32 tiles. Per-lane result layout of
// each tile is (row=l/4, col=l%4) — exactly the tf32 mma fragment layout.
#define LDSM_X4(r0, r1, r2, r3, addr) \
    asm volatile("ldmatrix.sync.aligned.m8n8.x4.shared.b16 {%0,%1,%2,%3}, [%4];" \
                 : "=r"(r0), "=r"(r1), "=r"(r2), "=r"(r3) : "r"(addr))

// TF32 mma.sync (m16n8k8): A row-major, B col-major, fp32 accum.
// A: a0=(g,t4) a1=(g+8,t4) a2=(g,t4+4) a3=(g+8,t4+4)
// B: b0=(k=t4,n=g) b1=(k=t4+4,n=g)
// C: c0=(g,2t4) c1=(g,2t4+1) c2=(g+8,2t4) c3=(g+8,2t4+1)
__device__ __forceinline__ void mma_tf32(float* d, const uint32_t* a,
                                         const uint32_t* b) {
    asm volatile(
        "mma.sync.aligned.m16n8k8.row.col.f32.tf32.tf32.f32 "
        "{%0,%1,%2,%3}, {%4,%5,%6,%7}, {%8,%9}, {%0,%1,%2,%3};"
        : "+f"(d[0]), "+f"(d[1]), "+f"(d[2]), "+f"(d[3])
        : "r"(a[0]), "r"(a[1]), "r"(a[2]), "r"(a[3]), "r"(b[0]), "r"(b[1]));
}

// ===========================================================================
// Prepass: round fp32 -> tf32 bit patterns
// ===========================================================================
__global__ void round_kernel(const float* __restrict__ src,
                             float* __restrict__ dst, int n4)
{
    const int stride = gridDim.x * blockDim.x;
    for (int i = blockIdx.x * blockDim.x + threadIdx.x; i < n4; i += stride)
        ((float4*)dst)[i] = tf32_rna4(((const float4*)src)[i]);
}

// ===========================================================================
// GEMM: C[128x128] = A[128xK] . W[128xK]^T + bias.  K = 1024.
// Single-buffer register-staged (R9 structure), ldmatrix fragment loads.
// 256 threads, 8 warps 2(M) x 4(N); warp tile 64x32 (4x4 m16n8 tiles).
// ===========================================================================
#define GEMM_K 1024
#define ASTR   36

template <int MODE>
__global__ __launch_bounds__(256, 2) void tc_gemm_kernel(
    const float* __restrict__ A, const float* __restrict__ W,
    const float* __restrict__ bias, float* __restrict__ out)
{
    __shared__ float As[128 * ASTR];
    __shared__ float Bs[128 * ASTR];
    const uint32_t sbA = smem_u32(As);
    const uint32_t sbB = smem_u32(Bs);

    const int tid = threadIdx.x;
    const int wid = tid >> 5;
    const int lane = tid & 31;
    const int g = lane >> 2;
    const int t4 = lane & 3;
    const int warpM = wid >> 2;       // 0..1
    const int warpN = wid & 3;        // 0..3
    const int m0 = blockIdx.y << 7;
    const int n0 = blockIdx.x << 7;

    // ldmatrix per-lane addressing
    const int l15 = lane & 15;
    const int aColAdd = (lane >> 4) << 2;                     // 0 | 4
    const int bRowOff = ((lane >> 4) << 3) + (lane & 7);      // pair-block row
    const int bColAdd = ((lane >> 3) & 1) << 2;               // 0 | 4

    const float* aBase = A + (size_t)m0 * GEMM_K;
    const float* wBase = W + (size_t)n0 * GEMM_K;

    float acc[4][4][4] = {};

    for (int s = 0; s < GEMM_K / 32; ++s) {
        const int k0 = s * 32;
        // Stage A/B tiles (inputs pre-rounded; compiler hoists LDGs)
        #pragma unroll
        for (int i = 0; i < 4; ++i) {
            const int e = tid + i * 256;
            const int row = e >> 3;
            const int c4 = e & 7;
            *(float4*)&As[row * ASTR + c4 * 4] =
                *(const float4*)(aBase + (size_t)row * GEMM_K + k0 + c4 * 4);
            *(float4*)&Bs[row * ASTR + c4 * 4] =
                *(const float4*)(wBase + (size_t)row * GEMM_K + k0 + c4 * 4);
        }
        __syncthreads();

        #pragma unroll
        for (int kc = 0; kc < 4; ++kc) {
            uint32_t afr[4][4], bfr[4][2];
            #pragma unroll
            for (int mt = 0; mt < 4; ++mt) {
                const uint32_t a = sbA +
                    ((warpM * 64 + mt * 16 + l15) * ASTR + kc * 8 + aColAdd) * 4u;
                LDSM_X4(afr[mt][0], afr[mt][1], afr[mt][2], afr[mt][3], a);
            }
            #pragma unroll
            for (int ntp = 0; ntp < 2; ++ntp) {
                const uint32_t a = sbB +
                    ((warpN * 32 + ntp * 16 + bRowOff) * ASTR + kc * 8 + bColAdd) * 4u;
                LDSM_X4(bfr[2 * ntp][0], bfr[2 * ntp][1],
                        bfr[2 * ntp + 1][0], bfr[2 * ntp + 1][1], a);
            }
            #pragma unroll
            for (int mt = 0; mt < 4; ++mt)
                #pragma unroll
                for (int nt = 0; nt < 4; ++nt)
                    mma_tf32(acc[mt][nt], afr[mt], bfr[nt]);
        }
        __syncthreads();
    }

    // Epilogue
    #pragma unroll
    for (int mt = 0; mt < 4; ++mt) {
        const int r0 = m0 + warpM * 64 + mt * 16 + g;
        const int r1 = r0 + 8;
        #pragma unroll
        for (int nt = 0; nt < 4; ++nt) {
            const int n = n0 + warpN * 32 + nt * 8 + t4 * 2;
            const float bn0 = bias[n], bn1 = bias[n + 1];
            const float v00 = acc[mt][nt][0] + bn0;
            const float v01 = acc[mt][nt][1] + bn1;
            const float v10 = acc[mt][nt][2] + bn0;
            const float v11 = acc[mt][nt][3] + bn1;
            if (MODE == 0) {
                // round at producer: flash consumes tf32 operands directly
                const int which = n >> 10;
                const int rn = n & 1023;
                const int h = rn >> 6;
                const int d = rn & 63;
                const int b = r0 >> 11;
                const size_t base = ((((size_t)which * BB + b) * HH + h) * SS);
                size_t i0 = (base + (r0 & 2047)) * HD + d;
                size_t i1 = (base + (r1 & 2047)) * HD + d;
                g_qkv[i0] = tf32_rna(v00); g_qkv[i0 + 1] = tf32_rna(v01);
                g_qkv[i1] = tf32_rna(v10); g_qkv[i1 + 1] = tf32_rna(v11);
            } else {
                out[(size_t)r0 * DD + n] = v00;
                out[(size_t)r0 * DD + n + 1] = v01;
                out[(size_t)r1 * DD + n] = v10;
                out[(size_t)r1 * DD + n + 1] = v11;
            }
        }
    }
}

// ===========================================================================
// Flash attention, mma.sync TF32 + ldmatrix (K frags, Q frags, P frags).
// 128 queries x 64 keys per tile. 256 threads; warp w owns q-rows w*16..+15.
// Q frags in registers; Q smem region reused as P buffer (warp-private rows).
// grid = (S/128, B*H) = (16, 32).
// ===========================================================================
#define FSTR 68
#define FLASH_SMEM ((128 + 64 + 64) * FSTR * (int)sizeof(float))   // 69632

__global__ __launch_bounds__(256, 2) void flash_attn_kernel()
{
    extern __shared__ float sm[];
    float* QP = sm;                       // [128][FSTR]  Q, then P
    float* Ks = sm + 128 * FSTR;          // [64][FSTR]
    float* Vs = Ks + 64 * FSTR;           // [64][FSTR]
    const uint32_t sbQP = smem_u32(QP);
    const uint32_t sbK = smem_u32(Ks);

    const int tid = threadIdx.x;
    const int wid = tid >> 5;
    const int lane = tid & 31;
    const int g = lane >> 2;
    const int t4 = lane & 3;
    const int q0 = blockIdx.x << 7;
    const int bh = blockIdx.y;
    const int b = bh >> 4, h = bh & 15;

    const int l15 = lane & 15;
    const int aColAdd = (lane >> 4) << 2;
    const int bRowOff = ((lane >> 4) << 3) + (lane & 7);
    const int bColAdd = ((lane >> 3) & 1) << 2;

    const size_t head_off = (size_t)(b * HH + h) * HEAD_ELEMS;
    const float* Qg = g_qkv + head_off;
    const float* Kg = g_qkv + QKV_ONE + head_off;
    const float* Vg = g_qkv + 2 * QKV_ONE + head_off;

    // Stage Q tile [128][64] (already tf32-rounded by producer)
    #pragma unroll
    for (int i = 0; i < 8; ++i) {
        const int e = tid + i * 256;
        const int row = e >> 4;
        const int c4 = e & 15;
        *(float4*)&QP[row * FSTR + c4 * 4] =
            *(const float4*)(Qg + (size_t)(q0 + row) * HD + c4 * 4);
    }
    __syncthreads();

    // Q fragments for all 8 k-chunks via ldmatrix (warp-private rows)
    uint32_t qf[8][4];
    #pragma unroll
    for (int kc = 0; kc < 8; ++kc) {
        const uint32_t a = sbQP +
            ((wid * 16 + l15) * FSTR + kc * 8 + aColAdd) * 4u;
        LDSM_X4(qf[kc][0], qf[kc][1], qf[kc][2], qf[kc][3], a);
    }

    float oacc[8][4] = {};
    float mr0 = -1e30f, mr1 = -1e30f, l0 = 0.0f, l1 = 0.0f;
    const float scale = 0.125f;

    for (int kt = 0; kt < SS / 64; ++kt) {
        __syncthreads();    // prior-iter K/V reads done before overwrite

        // Stage K,V tiles [64][64] (pre-rounded)
        #pragma unroll
        for (int i = 0; i < 4; ++i) {
            const int e = tid + i * 256;
            const int row = e >> 4;
            const int c4 = e & 15;
            const size_t gi = (size_t)(kt * 64 + row) * HD + c4 * 4;
            *(float4*)&Ks[row * FSTR + c4 * 4] = *(const float4*)(Kg + gi);
            *(float4*)&Vs[row * FSTR + c4 * 4] = *(const float4*)(Vg + gi);
        }
        __syncthreads();

        // S = Q . K^T : warp computes 16x64 scores; K frags via ldmatrix
        float sacc[8][4] = {};
        #pragma unroll
        for (int kc = 0; kc < 8; ++kc) {
            uint32_t bfr[8][2];
            #pragma unroll
            for (int ntp = 0; ntp < 4; ++ntp) {
                const uint32_t a = sbK +
                    ((ntp * 16 + bRowOff) * FSTR + kc * 8 + bColAdd) * 4u;
                LDSM_X4(bfr[2 * ntp][0], bfr[2 * ntp][1],
                        bfr[2 * ntp + 1][0], bfr[2 * ntp + 1][1], a);
            }
            #pragma unroll
            for (int nt = 0; nt < 8; ++nt)
                mma_tf32(sacc[nt], qf[kc], bfr[nt]);
        }

        // Online softmax. Row g: regs [0],[1]; row g+8: regs [2],[3].
        float mx0 = -1e30f, mx1 = -1e30f;
        #pragma unroll
        for (int nt = 0; nt < 8; ++nt) {
            sacc[nt][0] *= scale; sacc[nt][1] *= scale;
            sacc[nt][2] *= scale; sacc[nt][3] *= scale;
            mx0 = fmaxf(mx0, fmaxf(sacc[nt][0], sacc[nt][1]));
            mx1 = fmaxf(mx1, fmaxf(sacc[nt][2], sacc[nt][3]));
        }
        mx0 = fmaxf(mx0, __shfl_xor_sync(0xffffffffu, mx0, 1));
        mx0 = fmaxf(mx0, __shfl_xor_sync(0xffffffffu, mx0, 2));
        mx1 = fmaxf(mx1, __shfl_xor_sync(0xffffffffu, mx1, 1));
        mx1 = fmaxf(mx1, __shfl_xor_sync(0xffffffffu, mx1, 2));

        const float mn0 = fmaxf(mr0, mx0);
        const float mn1 = fmaxf(mr1, mx1);
        const float corr0 = __expf(mr0 - mn0);
        const float corr1 = __expf(mr1 - mn1);
        mr0 = mn0; mr1 = mn1;

        float rs0 = 0.0f, rs1 = 0.0f;
        #pragma unroll
        for (int nt = 0; nt < 8; ++nt) {
            sacc[nt][0] = __expf(sacc[nt][0] - mn0);
            sacc[nt][1] = __expf(sacc[nt][1] - mn0);
            sacc[nt][2] = __expf(sacc[nt][2] - mn1);
            sacc[nt][3] = __expf(sacc[nt][3] - mn1);
            rs0 += sacc[nt][0] + sacc[nt][1];
            rs1 += sacc[nt][2] + sacc[nt][3];
        }
        rs0 += __shfl_xor_sync(0xffffffffu, rs0, 1);
        rs0 += __shfl_xor_sync(0xffffffffu, rs0, 2);
        rs1 += __shfl_xor_sync(0xffffffffu, rs1, 1);
        rs1 += __shfl_xor_sync(0xffffffffu, rs1, 2);

        l0 = l0 * corr0 + rs0;
        l1 = l1 * corr1 + rs1;

        #pragma unroll
        for (int nt = 0; nt < 8; ++nt) {
            oacc[nt][0] *= corr0; oacc[nt][1] *= corr0;
            oacc[nt][2] *= corr1; oacc[nt][3] *= corr1;
        }

        // P -> smem (warp-private rows; QP reused), rounded to tf32
        __syncwarp();
        {
            const int row = wid * 16 + g;
            #pragma unroll
            for (int nt = 0; nt < 8; ++nt) {
                const int col = nt * 8 + t4 * 2;
                QP[row * FSTR + col]           = tf32_rna(sacc[nt][0]);
                QP[row * FSTR + col + 1]       = tf32_rna(sacc[nt][1]);
                QP[(row + 8) * FSTR + col]     = tf32_rna(sacc[nt][2]);
                QP[(row + 8) * FSTR + col + 1] = tf32_rna(sacc[nt][3]);
            }
        }
        __syncwarp();

        // O += P . V   (P frags via ldmatrix; V frags scalar — needs transpose)
        #pragma unroll
        for (int kc = 0; kc < 8; ++kc) {
            uint32_t af[4];
            const uint32_t a = sbQP +
                ((wid * 16 + l15) * FSTR + kc * 8 + aColAdd) * 4u;
            LDSM_X4(af[0], af[1], af[2], af[3], a);
            #pragma unroll
            for (int nt = 0; nt < 8; ++nt) {
                const float* vp = &Vs[(kc * 8 + t4) * FSTR + nt * 8 + g];
                uint32_t bfr[2];
                bfr[0] = __float_as_uint(vp[0]);
                bfr[1] = __float_as_uint(vp[4 * FSTR]);
                mma_tf32(oacc[nt], af, bfr);
            }
        }
    }

    // Epilogue: normalize, round (feeds proj GEMM), write [B,S,H*hd]
    const float inv0 = 1.0f / l0;
    const float inv1 = 1.0f / l1;
    const int row0 = q0 + wid * 16 + g;
    const int row1 = row0 + 8;
    #pragma unroll
    for (int nt = 0; nt < 8; ++nt) {
        const int col = h * HD + nt * 8 + t4 * 2;
        float* o0 = &g_attn[((size_t)b * SS + row0) * DD + col];
        float* o1 = &g_attn[((size_t)b * SS + row1) * DD + col];
        o0[0] = tf32_rna(oacc[nt][0] * inv0); o0[1] = tf32_rna(oacc[nt][1] * inv0);
        o1[0] = tf32_rna(oacc[nt][2] * inv1); o1[1] = tf32_rna(oacc[nt][3] * inv1);
    }
}

// ---------------------------------------------------------------------------
// Launch
// ---------------------------------------------------------------------------
extern "C" void kernel_launch(void* const* d_in, const int* in_sizes, int n_in,
                              void* d_out, int out_size)
{
    (void)in_sizes; (void)n_in; (void)out_size;
    const float* x      = (const float*)d_in[0];
    const float* w_qkv  = (const float*)d_in[1];
    const float* b_qkv  = (const float*)d_in[2];
    const float* w_proj = (const float*)d_in[3];
    const float* b_proj = (const float*)d_in[4];
    float* out = (float*)d_out;

    cudaFuncSetAttribute(flash_attn_kernel,
                         cudaFuncAttributeMaxDynamicSharedMemorySize,
                         FLASH_SMEM);

    float *xr, *wq, *wp, *attn_ptr;
    cudaGetSymbolAddress((void**)&xr, g_xr);
    cudaGetSymbolAddress((void**)&wq, g_wq);
    cudaGetSymbolAddress((void**)&wp, g_wp);
    cudaGetSymbolAddress((void**)&attn_ptr, g_attn);

    // 0) Pre-round inputs to tf32 (keeps all cvts out of mainloops)
    round_kernel<<<1024, 256>>>(x, xr, BB * SS * DD / 4);
    round_kernel<<<1024, 256>>>(w_qkv, wq, 3 * DD * DD / 4);
    round_kernel<<<512, 256>>>(w_proj, wp, DD * DD / 4);

    // 1) QKV projection: M=4096, N=3072 -> grid (24, 32)
    tc_gemm_kernel<0><<<dim3(3 * DD / 128, BB * SS / 128), 256>>>(
        xr, wq, b_qkv, nullptr);

    // 2) Flash attention: grid (16, 32)
    flash_attn_kernel<<<dim3(SS / 128, BB * HH), 256, FLASH_SMEM>>>();

    // 3) Output projection: M=4096, N=1024 -> grid (8, 32)
    tc_gemm_kernel<1><<<dim3(DD / 128, BB * SS / 128), 256>>>(
        attn_ptr, wp, b_proj, out);
}

// round 17
// speedup vs baseline: 1.1992x; 1.0213x over previous
#include <cuda_runtime.h>
#include <cstdint>
#include <math.h>

// Problem constants
#define BB 2
#define SS 2048
#define DD 1024
#define HH 16
#define HD 64

// Scratch (allocation-free rule: __device__ globals)
__device__ float g_qkv[(size_t)3 * BB * HH * SS * HD];   // [3][B][H][S][HD] (tf32-rounded)
__device__ float g_attn[(size_t)BB * SS * DD];           // [B][S][D]       (tf32-rounded)
__device__ float g_xr[(size_t)BB * SS * DD];             // rounded x
__device__ float g_wq[(size_t)3 * DD * DD];              // rounded w_qkv
__device__ float g_wp[(size_t)DD * DD];                  // rounded w_proj

#define HEAD_ELEMS ((size_t)SS * HD)
#define QKV_ONE    ((size_t)BB * HH * SS * HD)

// ===========================================================================
// Helpers
// ===========================================================================
__device__ __forceinline__ uint32_t smem_u32(const void* p) {
    uint32_t a;
    asm("{ .reg .u64 t; cvta.to.shared.u64 t, %1; cvt.u32.u64 %0, t; }"
        : "=r"(a) : "l"(p));
    return a;
}
__device__ __forceinline__ float tf32_rna(float x) {
    uint32_t u;
    asm("cvt.rna.tf32.f32 %0, %1;" : "=r"(u) : "f"(x));
    return __uint_as_float(u);
}
__device__ __forceinline__ float4 tf32_rna4(float4 v) {
    v.x = tf32_rna(v.x); v.y = tf32_rna(v.y);
    v.z = tf32_rna(v.z); v.w = tf32_rna(v.w);
    return v;
}
// Raw exp2 (what __expf lowers to, minus the log2e FMUL we fold into scale)
__device__ __forceinline__ float ex2(float x) {
    float y;
    asm("ex2.approx.f32 %0, %1;" : "=f"(y) : "f"(x));
    return y;
}

#define CP_ASYNC16(saddr, gptr) \
    asm volatile("cp.async.ca.shared.global [%0], [%1], 16;" \
                 :: "r"(saddr), "l"(gptr) : "memory")
#define CP_COMMIT() asm volatile("cp.async.commit_group;" ::: "memory")
#define CP_WAIT1()  asm volatile("cp.async.wait_group 1;" ::: "memory")
#define CP_WAIT0()  asm volatile("cp.async.wait_group 0;" ::: "memory")

// ldmatrix x4: 4 8x8 b16 tiles == 4 8x4 f32 tiles; per-lane layout of each
// tile is (row=l/4, col=l%4) — exactly the tf32 mma fragment layout.
#define LDSM_X4(r0, r1, r2, r3, addr) \
    asm volatile("ldmatrix.sync.aligned.m8n8.x4.shared.b16 {%0,%1,%2,%3}, [%4];" \
                 : "=r"(r0), "=r"(r1), "=r"(r2), "=r"(r3) : "r"(addr))

// TF32 mma.sync (m16n8k8): A row-major, B col-major, fp32 accum.
// A: a0=(g,t4) a1=(g+8,t4) a2=(g,t4+4) a3=(g+8,t4+4)
// B: b0=(k=t4,n=g) b1=(k=t4+4,n=g)
// C: c0=(g,2t4) c1=(g,2t4+1) c2=(g+8,2t4) c3=(g+8,2t4+1)
__device__ __forceinline__ void mma_tf32(float* d, const uint32_t* a,
                                         const uint32_t* b) {
    asm volatile(
        "mma.sync.aligned.m16n8k8.row.col.f32.tf32.tf32.f32 "
        "{%0,%1,%2,%3}, {%4,%5,%6,%7}, {%8,%9}, {%0,%1,%2,%3};"
        : "+f"(d[0]), "+f"(d[1]), "+f"(d[2]), "+f"(d[3])
        : "r"(a[0]), "r"(a[1]), "r"(a[2]), "r"(a[3]), "r"(b[0]), "r"(b[1]));
}

// ===========================================================================
// Prepass: round fp32 -> tf32 bit patterns
// ===========================================================================
__global__ void round_kernel(const float* __restrict__ src,
                             float* __restrict__ dst, int n4)
{
    const int stride = gridDim.x * blockDim.x;
    for (int i = blockIdx.x * blockDim.x + threadIdx.x; i < n4; i += stride)
        ((float4*)dst)[i] = tf32_rna4(((const float4*)src)[i]);
}

// ===========================================================================
// GEMM: C[128x128] = A[128xK] . W[128xK]^T + bias.  K = 1024.
// 3-stage cp.async ring, ONE __syncthreads per stage (wait_group->barrier
// idiom). stage s+2 issued at end of iter s -> ~2 compute phases of latency
// hiding. ldmatrix fragment loads. 8 warps 2(M) x 4(N), warp tile 64x32.
// ===========================================================================
#define GEMM_K   1024
#define ASTR     36
#define GTILE    (128 * ASTR)                  // floats per (A or B) buffer
#define NSTG     3
#define NSTAGES  (GEMM_K / 32)                 // 32
#define GEMM_SMEM (NSTG * 2 * GTILE * (int)sizeof(float))   // 110592 B

template <int MODE>
__global__ __launch_bounds__(256, 2) void tc_gemm_kernel(
    const float* __restrict__ A, const float* __restrict__ W,
    const float* __restrict__ bias, float* __restrict__ out)
{
    extern __shared__ float smem[];
    const uint32_t sb = smem_u32(smem);

    const int tid = threadIdx.x;
    const int wid = tid >> 5;
    const int lane = tid & 31;
    const int g = lane >> 2;
    const int t4 = lane & 3;
    const int warpM = wid >> 2;       // 0..1
    const int warpN = wid & 3;        // 0..3
    const int m0 = blockIdx.y << 7;
    const int n0 = blockIdx.x << 7;

    // ldmatrix per-lane addressing
    const int l15 = lane & 15;
    const int aColAdd = (lane >> 4) << 2;                     // 0 | 4
    const int bRowOff = ((lane >> 4) << 3) + (lane & 7);      // pair-block row
    const int bColAdd = ((lane >> 3) & 1) << 2;               // 0 | 4

    const float* aBase = A + (size_t)m0 * GEMM_K;
    const float* wBase = W + (size_t)n0 * GEMM_K;

    const int srow = tid >> 3;       // 0..31 (stride 32 over 4 iters)
    const int sc4 = tid & 7;

    auto stage = [&](int s, int bsel) {
        const int k0 = s * 32;
        const uint32_t sA = sb + (uint32_t)(bsel * 2 * GTILE) * 4u;
        const uint32_t sB = sA + (uint32_t)GTILE * 4u;
        #pragma unroll
        for (int i = 0; i < 4; ++i) {
            const int row = srow + i * 32;
            const uint32_t so = (uint32_t)(row * ASTR + sc4 * 4) * 4u;
            CP_ASYNC16(sA + so, aBase + (size_t)row * GEMM_K + k0 + sc4 * 4);
            CP_ASYNC16(sB + so, wBase + (size_t)row * GEMM_K + k0 + sc4 * 4);
        }
        CP_COMMIT();
    };

    float acc[4][4][4] = {};

    stage(0, 0);
    stage(1, 1);

    int bsel = 0;       // buffer of stage s
    int nsel = 2;       // buffer for stage s+2
    for (int s = 0; s < NSTAGES; ++s) {
        if (s == NSTAGES - 1) { CP_WAIT0(); } else { CP_WAIT1(); }
        __syncthreads();   // publish stage s to all threads; also guarantees
                           // all reads of buffer (s-1)%3 finished (stage s+2
                           // below reuses it)

        const uint32_t sbA = sb + (uint32_t)(bsel * 2 * GTILE) * 4u;
        const uint32_t sbB = sbA + (uint32_t)GTILE * 4u;

        #pragma unroll
        for (int kc = 0; kc < 4; ++kc) {
            uint32_t afr[4][4], bfr[4][2];
            #pragma unroll
            for (int mt = 0; mt < 4; ++mt) {
                const uint32_t a = sbA +
                    ((warpM * 64 + mt * 16 + l15) * ASTR + kc * 8 + aColAdd) * 4u;
                LDSM_X4(afr[mt][0], afr[mt][1], afr[mt][2], afr[mt][3], a);
            }
            #pragma unroll
            for (int ntp = 0; ntp < 2; ++ntp) {
                const uint32_t a = sbB +
                    ((warpN * 32 + ntp * 16 + bRowOff) * ASTR + kc * 8 + bColAdd) * 4u;
                LDSM_X4(bfr[2 * ntp][0], bfr[2 * ntp][1],
                        bfr[2 * ntp + 1][0], bfr[2 * ntp + 1][1], a);
            }
            #pragma unroll
            for (int mt = 0; mt < 4; ++mt)
                #pragma unroll
                for (int nt = 0; nt < 4; ++nt)
                    mma_tf32(acc[mt][nt], afr[mt], bfr[nt]);
        }

        if (s + 2 < NSTAGES) stage(s + 2, nsel);
        bsel = (bsel == 2) ? 0 : bsel + 1;
        nsel = (nsel == 2) ? 0 : nsel + 1;
    }

    // Epilogue
    #pragma unroll
    for (int mt = 0; mt < 4; ++mt) {
        const int r0 = m0 + warpM * 64 + mt * 16 + g;
        const int r1 = r0 + 8;
        #pragma unroll
        for (int nt = 0; nt < 4; ++nt) {
            const int n = n0 + warpN * 32 + nt * 8 + t4 * 2;
            const float bn0 = bias[n], bn1 = bias[n + 1];
            const float v00 = acc[mt][nt][0] + bn0;
            const float v01 = acc[mt][nt][1] + bn1;
            const float v10 = acc[mt][nt][2] + bn0;
            const float v11 = acc[mt][nt][3] + bn1;
            if (MODE == 0) {
                // round at producer: flash consumes tf32 operands directly
                const int which = n >> 10;
                const int rn = n & 1023;
                const int h = rn >> 6;
                const int d = rn & 63;
                const int b = r0 >> 11;
                const size_t base = ((((size_t)which * BB + b) * HH + h) * SS);
                size_t i0 = (base + (r0 & 2047)) * HD + d;
                size_t i1 = (base + (r1 & 2047)) * HD + d;
                g_qkv[i0] = tf32_rna(v00); g_qkv[i0 + 1] = tf32_rna(v01);
                g_qkv[i1] = tf32_rna(v10); g_qkv[i1 + 1] = tf32_rna(v11);
            } else {
                out[(size_t)r0 * DD + n] = v00;
                out[(size_t)r0 * DD + n + 1] = v01;
                out[(size_t)r1 * DD + n] = v10;
                out[(size_t)r1 * DD + n + 1] = v11;
            }
        }
    }
}

// ===========================================================================
// Flash attention, mma.sync TF32 + ldmatrix (K/Q/P frags). Softmax in
// log2-domain: log2e folded into scale, raw ex2 (no per-exp FMUL).
// 128 queries x 64 keys per tile. 256 threads; warp w owns q-rows w*16..+15.
// grid = (S/128, B*H) = (16, 32).
// ===========================================================================
#define FSTR 68
#define FLASH_SMEM ((128 + 64 + 64) * FSTR * (int)sizeof(float))   // 69632

__global__ __launch_bounds__(256, 2) void flash_attn_kernel()
{
    extern __shared__ float sm[];
    float* QP = sm;                       // [128][FSTR]  Q, then P
    float* Ks = sm + 128 * FSTR;          // [64][FSTR]
    float* Vs = Ks + 64 * FSTR;           // [64][FSTR]
    const uint32_t sbQP = smem_u32(QP);
    const uint32_t sbK = smem_u32(Ks);

    const int tid = threadIdx.x;
    const int wid = tid >> 5;
    const int lane = tid & 31;
    const int g = lane >> 2;
    const int t4 = lane & 3;
    const int q0 = blockIdx.x << 7;
    const int bh = blockIdx.y;
    const int b = bh >> 4, h = bh & 15;

    const int l15 = lane & 15;
    const int aColAdd = (lane >> 4) << 2;
    const int bRowOff = ((lane >> 4) << 3) + (lane & 7);
    const int bColAdd = ((lane >> 3) & 1) << 2;

    const size_t head_off = (size_t)(b * HH + h) * HEAD_ELEMS;
    const float* Qg = g_qkv + head_off;
    const float* Kg = g_qkv + QKV_ONE + head_off;
    const float* Vg = g_qkv + 2 * QKV_ONE + head_off;

    // Stage Q tile [128][64] (already tf32-rounded by producer)
    #pragma unroll
    for (int i = 0; i < 8; ++i) {
        const int e = tid + i * 256;
        const int row = e >> 4;
        const int c4 = e & 15;
        *(float4*)&QP[row * FSTR + c4 * 4] =
            *(const float4*)(Qg + (size_t)(q0 + row) * HD + c4 * 4);
    }
    __syncthreads();

    // Q fragments for all 8 k-chunks via ldmatrix (warp-private rows)
    uint32_t qf[8][4];
    #pragma unroll
    for (int kc = 0; kc < 8; ++kc) {
        const uint32_t a = sbQP +
            ((wid * 16 + l15) * FSTR + kc * 8 + aColAdd) * 4u;
        LDSM_X4(qf[kc][0], qf[kc][1], qf[kc][2], qf[kc][3], a);
    }

    float oacc[8][4] = {};
    float mr0 = -1e30f, mr1 = -1e30f, l0 = 0.0f, l1 = 0.0f;
    // 1/sqrt(64) * log2(e): scores land in log2-domain; ex2 recovers exp()
    const float scale = 0.125f * 1.44269504f;

    for (int kt = 0; kt < SS / 64; ++kt) {
        __syncthreads();    // prior-iter K/V reads done before overwrite

        // Stage K,V tiles [64][64] (pre-rounded)
        #pragma unroll
        for (int i = 0; i < 4; ++i) {
            const int e = tid + i * 256;
            const int row = e >> 4;
            const int c4 = e & 15;
            const size_t gi = (size_t)(kt * 64 + row) * HD + c4 * 4;
            *(float4*)&Ks[row * FSTR + c4 * 4] = *(const float4*)(Kg + gi);
            *(float4*)&Vs[row * FSTR + c4 * 4] = *(const float4*)(Vg + gi);
        }
        __syncthreads();

        // S = Q . K^T : warp computes 16x64 scores; K frags via ldmatrix
        float sacc[8][4] = {};
        #pragma unroll
        for (int kc = 0; kc < 8; ++kc) {
            uint32_t bfr[8][2];
            #pragma unroll
            for (int ntp = 0; ntp < 4; ++ntp) {
                const uint32_t a = sbK +
                    ((ntp * 16 + bRowOff) * FSTR + kc * 8 + bColAdd) * 4u;
                LDSM_X4(bfr[2 * ntp][0], bfr[2 * ntp][1],
                        bfr[2 * ntp + 1][0], bfr[2 * ntp + 1][1], a);
            }
            #pragma unroll
            for (int nt = 0; nt < 8; ++nt)
                mma_tf32(sacc[nt], qf[kc], bfr[nt]);
        }

        // Online softmax (log2-domain). Row g: regs [0],[1]; row g+8: [2],[3].
        float mx0 = -1e30f, mx1 = -1e30f;
        #pragma unroll
        for (int nt = 0; nt < 8; ++nt) {
            sacc[nt][0] *= scale; sacc[nt][1] *= scale;
            sacc[nt][2] *= scale; sacc[nt][3] *= scale;
            mx0 = fmaxf(mx0, fmaxf(sacc[nt][0], sacc[nt][1]));
            mx1 = fmaxf(mx1, fmaxf(sacc[nt][2], sacc[nt][3]));
        }
        mx0 = fmaxf(mx0, __shfl_xor_sync(0xffffffffu, mx0, 1));
        mx0 = fmaxf(mx0, __shfl_xor_sync(0xffffffffu, mx0, 2));
        mx1 = fmaxf(mx1, __shfl_xor_sync(0xffffffffu, mx1, 1));
        mx1 = fmaxf(mx1, __shfl_xor_sync(0xffffffffu, mx1, 2));

        const float mn0 = fmaxf(mr0, mx0);
        const float mn1 = fmaxf(mr1, mx1);
        const float corr0 = ex2(mr0 - mn0);
        const float corr1 = ex2(mr1 - mn1);
        mr0 = mn0; mr1 = mn1;

        float rs0 = 0.0f, rs1 = 0.0f;
        #pragma unroll
        for (int nt = 0; nt < 8; ++nt) {
            sacc[nt][0] = ex2(sacc[nt][0] - mn0);
            sacc[nt][1] = ex2(sacc[nt][1] - mn0);
            sacc[nt][2] = ex2(sacc[nt][2] - mn1);
            sacc[nt][3] = ex2(sacc[nt][3] - mn1);
            rs0 += sacc[nt][0] + sacc[nt][1];
            rs1 += sacc[nt][2] + sacc[nt][3];
        }
        rs0 += __shfl_xor_sync(0xffffffffu, rs0, 1);
        rs0 += __shfl_xor_sync(0xffffffffu, rs0, 2);
        rs1 += __shfl_xor_sync(0xffffffffu, rs1, 1);
        rs1 += __shfl_xor_sync(0xffffffffu, rs1, 2);

        l0 = l0 * corr0 + rs0;
        l1 = l1 * corr1 + rs1;

        #pragma unroll
        for (int nt = 0; nt < 8; ++nt) {
            oacc[nt][0] *= corr0; oacc[nt][1] *= corr0;
            oacc[nt][2] *= corr1; oacc[nt][3] *= corr1;
        }

        // P -> smem (warp-private rows; QP reused), rounded to tf32
        __syncwarp();
        {
            const int row = wid * 16 + g;
            #pragma unroll
            for (int nt = 0; nt < 8; ++nt) {
                const int col = nt * 8 + t4 * 2;
                QP[row * FSTR + col]           = tf32_rna(sacc[nt][0]);
                QP[row * FSTR + col + 1]       = tf32_rna(sacc[nt][1]);
                QP[(row + 8) * FSTR + col]     = tf32_rna(sacc[nt][2]);
                QP[(row + 8) * FSTR + col + 1] = tf32_rna(sacc[nt][3]);
            }
        }
        __syncwarp();

        // O += P . V   (P frags via ldmatrix; V frags scalar — needs transpose)
        #pragma unroll
        for (int kc = 0; kc < 8; ++kc) {
            uint32_t af[4];
            const uint32_t a = sbQP +
                ((wid * 16 + l15) * FSTR + kc * 8 + aColAdd) * 4u;
            LDSM_X4(af[0], af[1], af[2], af[3], a);
            #pragma unroll
            for (int nt = 0; nt < 8; ++nt) {
                const float* vp = &Vs[(kc * 8 + t4) * FSTR + nt * 8 + g];
                uint32_t bfr[2];
                bfr[0] = __float_as_uint(vp[0]);
                bfr[1] = __float_as_uint(vp[4 * FSTR]);
                mma_tf32(oacc[nt], af, bfr);
            }
        }
    }

    // Epilogue: normalize, round (feeds proj GEMM), write [B,S,H*hd]
    const float inv0 = 1.0f / l0;
    const float inv1 = 1.0f / l1;
    const int row0 = q0 + wid * 16 + g;
    const int row1 = row0 + 8;
    #pragma unroll
    for (int nt = 0; nt < 8; ++nt) {
        const int col = h * HD + nt * 8 + t4 * 2;
        float* o0 = &g_attn[((size_t)b * SS + row0) * DD + col];
        float* o1 = &g_attn[((size_t)b * SS + row1) * DD + col];
        o0[0] = tf32_rna(oacc[nt][0] * inv0); o0[1] = tf32_rna(oacc[nt][1] * inv0);
        o1[0] = tf32_rna(oacc[nt][2] * inv1); o1[1] = tf32_rna(oacc[nt][3] * inv1);
    }
}

// ---------------------------------------------------------------------------
// Launch
// ---------------------------------------------------------------------------
extern "C" void kernel_launch(void* const* d_in, const int* in_sizes, int n_in,
                              void* d_out, int out_size)
{
    (void)in_sizes; (void)n_in; (void)out_size;
    const float* x      = (const float*)d_in[0];
    const float* w_qkv  = (const float*)d_in[1];
    const float* b_qkv  = (const float*)d_in[2];
    const float* w_proj = (const float*)d_in[3];
    const float* b_proj = (const float*)d_in[4];
    float* out = (float*)d_out;

    cudaFuncSetAttribute(tc_gemm_kernel<0>,
                         cudaFuncAttributeMaxDynamicSharedMemorySize, GEMM_SMEM);
    cudaFuncSetAttribute(tc_gemm_kernel<1>,
                         cudaFuncAttributeMaxDynamicSharedMemorySize, GEMM_SMEM);
    cudaFuncSetAttribute(flash_attn_kernel,
                         cudaFuncAttributeMaxDynamicSharedMemorySize, FLASH_SMEM);

    float *xr, *wq, *wp, *attn_ptr;
    cudaGetSymbolAddress((void**)&xr, g_xr);
    cudaGetSymbolAddress((void**)&wq, g_wq);
    cudaGetSymbolAddress((void**)&wp, g_wp);
    cudaGetSymbolAddress((void**)&attn_ptr, g_attn);

    // 0) Pre-round inputs to tf32 (keeps all cvts out of mainloops)
    round_kernel<<<1024, 256>>>(x, xr, BB * SS * DD / 4);
    round_kernel<<<1024, 256>>>(w_qkv, wq, 3 * DD * DD / 4);
    round_kernel<<<512, 256>>>(w_proj, wp, DD * DD / 4);

    // 1) QKV projection: M=4096, N=3072 -> grid (24, 32)
    tc_gemm_kernel<0><<<dim3(3 * DD / 128, BB * SS / 128), 256, GEMM_SMEM>>>(
        xr, wq, b_qkv, nullptr);

    // 2) Flash attention: grid (16, 32)
    flash_attn_kernel<<<dim3(SS / 128, BB * HH), 256, FLASH_SMEM>>>();

    // 3) Output projection: M=4096, N=1024 -> grid (8, 32)
    tc_gemm_kernel<1><<<dim3(DD / 128, BB * SS / 128), 256, GEMM_SMEM>>>(
        attn_ptr, wp, b_proj, out);
}